// round 3
// baseline (speedup 1.0000x reference)
#include <cuda_runtime.h>
#include <cstdint>

// SimpleGNNBlock: out[b,k] = sum_p relu( relu(feats[b,p,:] @ W1 + b1) @ W2 + b2 )
// feats = [dx, dy, 1/sqrt(dx^2+dy^2+1e-6), m_p],  B=32768, P=128, H=64.
//
// R3: W2 MMA B-fragments hoisted to registers (loop-invariant, warp-identical)
//     -> removes the dominant shared-memory crossbar stream (64x LDS.64 per
//     warp per half). Epilogue reduction deferred to once per batch.

#define BATCHES 32768
#define PP 128
#define HH 64

#define GRID 4096
#define BPC (BATCHES / GRID)   // batches per CTA = 8

#define HS_STRIDE 68           // 68 % 32 == 4 -> conflict-free A-frag reads

__device__ __forceinline__ uint32_t f2tf32(float x) {
    uint32_t u;
    asm("cvt.rna.tf32.f32 %0, %1;" : "=r"(u) : "f"(x));
    return u;
}

__global__ __launch_bounds__(128, 2)
void gnn_kernel(const float* __restrict__ planet_xy,   // (B,P,2)
                const float* __restrict__ planet_m,    // (P)
                const float* __restrict__ ast_xy,      // (B,2)
                const float* __restrict__ W1,          // (4,H)
                const float* __restrict__ b1,          // (H)
                const float* __restrict__ W2,          // (H,H) [j][k]
                const float* __restrict__ b2,          // (H)
                float* __restrict__ out)               // (B,H)
{
    __shared__ float  h_s[64 * HS_STRIDE];   // half-batch of h rows (tf32 bits)
    __shared__ float4 feats_s[PP];
    __shared__ float  sacc[HH];
    __shared__ float  b2s[HH];

    const int tid  = threadIdx.x;
    const int lane = tid & 31;
    const int w    = tid >> 5;     // warp 0..3
    const int g    = lane >> 2;    // groupID 0..7
    const int tig  = lane & 3;     // thread-in-group 0..3

    // ---- W2 B-fragments, register-resident (loop-invariant, warp-identical).
    // m16n8k8.row.col B frag: thread holds B[k=tig][n=g], B[k=tig+4][n=g].
    // For n-tile n and k-tile kt: col = n*8+g, rows kt*8+tig and kt*8+tig+4.
    uint32_t brx[8][8], bry[8][8];
    #pragma unroll
    for (int kt = 0; kt < 8; ++kt) {
        #pragma unroll
        for (int n = 0; n < 8; ++n) {
            int col = n * 8 + g;
            brx[kt][n] = f2tf32(W2[(kt * 8 + tig)     * HH + col]);
            bry[kt][n] = f2tf32(W2[(kt * 8 + tig + 4) * HH + col]);
        }
    }
    if (tid < HH) b2s[tid] = b2[tid];

    // layer-1 per-thread constants: thread owns hidden channel kk = tid%64
    const int   kk  = tid & 63;
    const float w0  = W1[0 * HH + kk];
    const float w1  = W1[1 * HH + kk];
    const float w2  = W1[2 * HH + kk];
    const float w3  = W1[3 * HH + kk];
    const float b1v = b1[kk];
    const float mval = planet_m[tid];

    for (int it = 0; it < BPC; ++it) {
        const int b = blockIdx.x + it * GRID;

        // ---- feats: one thread per p ----
        if (tid < HH) sacc[tid] = 0.0f;
        float2 pxy = reinterpret_cast<const float2*>(planet_xy)[b * PP + tid];
        float ax = ast_xy[2 * b], ay = ast_xy[2 * b + 1];
        float dx = pxy.x - ax;
        float dy = pxy.y - ay;
        float inv = rsqrtf(fmaf(dx, dx, fmaf(dy, dy, 1e-6f)));
        feats_s[tid] = make_float4(dx, dy, inv, mval);
        __syncthreads();

        // per-batch partial sums (post-relu, accumulated over both halves)
        float s0[8], s1[8];
        #pragma unroll
        for (int n = 0; n < 8; ++n) { s0[n] = 0.f; s1[n] = 0.f; }

        #pragma unroll
        for (int half = 0; half < 2; ++half) {
            // ---- layer 1: 64 rows, thread owns channel kk ----
            {
                const int rbase = (tid >> 6) * 32;
                #pragma unroll 8
                for (int i = 0; i < 32; ++i) {
                    int row = rbase + i;
                    float4 f = feats_s[half * 64 + row];   // warp-uniform broadcast
                    float hv = fmaf(f.x, w0, b1v);
                    hv = fmaf(f.y, w1, hv);
                    hv = fmaf(f.z, w2, hv);
                    hv = fmaf(f.w, w3, hv);
                    hv = fmaxf(hv, 0.0f);
                    h_s[row * HS_STRIDE + kk] = __uint_as_float(f2tf32(hv));
                }
            }
            __syncthreads();

            // ---- layer 2: warp computes 16 rows x 64 cols, B from registers ----
            float c[8][4];
            #pragma unroll
            for (int n = 0; n < 8; ++n) {
                c[n][0] = 0.f; c[n][1] = 0.f; c[n][2] = 0.f; c[n][3] = 0.f;
            }
            const int r0 = w * 16 + g;
            #pragma unroll
            for (int kt = 0; kt < 8; ++kt) {
                uint32_t a0 = __float_as_uint(h_s[r0       * HS_STRIDE + kt * 8 + tig]);
                uint32_t a1 = __float_as_uint(h_s[(r0 + 8) * HS_STRIDE + kt * 8 + tig]);
                uint32_t a2 = __float_as_uint(h_s[r0       * HS_STRIDE + kt * 8 + tig + 4]);
                uint32_t a3 = __float_as_uint(h_s[(r0 + 8) * HS_STRIDE + kt * 8 + tig + 4]);
                #pragma unroll
                for (int n = 0; n < 8; ++n) {
                    asm volatile(
                        "mma.sync.aligned.m16n8k8.row.col.f32.tf32.tf32.f32 "
                        "{%0,%1,%2,%3}, {%4,%5,%6,%7}, {%8,%9}, {%0,%1,%2,%3};"
                        : "+f"(c[n][0]), "+f"(c[n][1]), "+f"(c[n][2]), "+f"(c[n][3])
                        : "r"(a0), "r"(a1), "r"(a2), "r"(a3),
                          "r"(brx[kt][n]), "r"(bry[kt][n]));
                }
            }

            // relu(+b2) and fold this half's 2 rows into the register partials
            #pragma unroll
            for (int n = 0; n < 8; ++n) {
                int col0 = n * 8 + 2 * tig;
                float bb0 = b2s[col0];
                float bb1 = b2s[col0 + 1];
                s0[n] += fmaxf(c[n][0] + bb0, 0.f) + fmaxf(c[n][2] + bb0, 0.f);
                s1[n] += fmaxf(c[n][1] + bb1, 0.f) + fmaxf(c[n][3] + bb1, 0.f);
            }
            __syncthreads();   // h_s fully consumed before next half rewrites
        }

        // ---- once per batch: cross-lane reduce over g, then cross-warp ----
        #pragma unroll
        for (int n = 0; n < 8; ++n) {
            float v0 = s0[n], v1 = s1[n];
            v0 += __shfl_xor_sync(0xffffffffu, v0, 4);
            v1 += __shfl_xor_sync(0xffffffffu, v1, 4);
            v0 += __shfl_xor_sync(0xffffffffu, v0, 8);
            v1 += __shfl_xor_sync(0xffffffffu, v1, 8);
            v0 += __shfl_xor_sync(0xffffffffu, v0, 16);
            v1 += __shfl_xor_sync(0xffffffffu, v1, 16);
            if (g == 0) {
                int col0 = n * 8 + 2 * tig;
                atomicAdd(&sacc[col0],     v0);
                atomicAdd(&sacc[col0 + 1], v1);
            }
        }
        __syncthreads();

        if (tid < HH) out[b * HH + tid] = sacc[tid];
        __syncthreads();
    }
}

extern "C" void kernel_launch(void* const* d_in, const int* in_sizes, int n_in,
                              void* d_out, int out_size) {
    (void)in_sizes; (void)n_in; (void)out_size;
    const float* planet_xy = (const float*)d_in[0];
    const float* planet_m  = (const float*)d_in[1];
    const float* ast_xy    = (const float*)d_in[2];
    const float* W1        = (const float*)d_in[3];
    const float* b1        = (const float*)d_in[4];
    const float* W2        = (const float*)d_in[5];
    const float* b2        = (const float*)d_in[6];
    float* out             = (float*)d_out;

    gnn_kernel<<<GRID, 128>>>(planet_xy, planet_m, ast_xy, W1, b1, W2, b2, out);
}

// round 4
// speedup vs baseline: 1.4293x; 1.4293x over previous
#include <cuda_runtime.h>
#include <cstdint>

// SimpleGNNBlock: out[b,k] = sum_p relu( relu(feats[b,p,:] @ W1 + b1) @ W2 + b2 )
// feats = [dx, dy, 1/sqrt(dx^2+dy^2+1e-6), m_p],  B=32768, P=128, H=64.
//
// R4: 256 threads / 8 warps per CTA. Each warp owns a 16-row x 32-col output
// tile -> B-fragments in registers shrink to 64/thread, restoring 4 warps/SMSP
// occupancy while keeping zero B shared-memory traffic.

#define BATCHES 32768
#define PP 128
#define HH 64

#define GRID 4096
#define BPC (BATCHES / GRID)   // 8 batches per CTA

#define HS_STRIDE 68           // 68 % 32 == 4 -> conflict-free A-frag reads

__device__ __forceinline__ uint32_t f2tf32(float x) {
    uint32_t u;
    asm("cvt.rna.tf32.f32 %0, %1;" : "=r"(u) : "f"(x));
    return u;
}

__global__ __launch_bounds__(256, 2)
void gnn_kernel(const float* __restrict__ planet_xy,   // (B,P,2)
                const float* __restrict__ planet_m,    // (P)
                const float* __restrict__ ast_xy,      // (B,2)
                const float* __restrict__ W1,          // (4,H)
                const float* __restrict__ b1,          // (H)
                const float* __restrict__ W2,          // (H,H) [j][k]
                const float* __restrict__ b2,          // (H)
                float* __restrict__ out)               // (B,H)
{
    __shared__ float  h_s[64 * HS_STRIDE];   // half-batch (64 rows) of h, tf32 bits
    __shared__ float4 feats_s[PP];
    __shared__ float  sacc[HH];
    __shared__ float  b2s[HH];

    const int tid  = threadIdx.x;
    const int lane = tid & 31;
    const int w    = tid >> 5;     // warp 0..7
    const int g    = lane >> 2;    // groupID 0..7
    const int tig  = lane & 3;     // thread-in-group 0..3

    const int mt = w & 3;          // m-tile 0..3 (rows mt*16 .. mt*16+15)
    const int nh = w >> 2;         // n-half 0..1 (cols nh*32 .. nh*32+31)

    // ---- W2 B-fragments for this warp's 4 n-tiles, register-resident ----
    // m16n8k8.row.col B frag: thread holds B[k=tig][n=g], B[k=tig+4][n=g]
    // where B[n][k] = W2[k][n]. Global n-tile = nh*4 + n.
    uint32_t brx[8][4], bry[8][4];
    #pragma unroll
    for (int kt = 0; kt < 8; ++kt) {
        #pragma unroll
        for (int n = 0; n < 4; ++n) {
            int col = (nh * 4 + n) * 8 + g;
            brx[kt][n] = f2tf32(W2[(kt * 8 + tig)     * HH + col]);
            bry[kt][n] = f2tf32(W2[(kt * 8 + tig + 4) * HH + col]);
        }
    }
    if (tid < HH) b2s[tid] = b2[tid];

    // layer-1 constants: thread owns hidden channel kk = tid%64,
    // row quarter = tid/64 (16 rows per half-batch).
    const int   kk  = tid & 63;
    const int   rq  = tid >> 6;    // 0..3
    const float w0  = W1[0 * HH + kk];
    const float w1  = W1[1 * HH + kk];
    const float w2  = W1[2 * HH + kk];
    const float w3  = W1[3 * HH + kk];
    const float b1v = b1[kk];
    float mval = 0.0f;
    if (tid < PP) mval = planet_m[tid];

    for (int it = 0; it < BPC; ++it) {
        const int b = blockIdx.x + it * GRID;

        // ---- feats: one thread per p (first 128 threads) ----
        if (tid < HH) sacc[tid] = 0.0f;
        if (tid < PP) {
            float2 pxy = reinterpret_cast<const float2*>(planet_xy)[b * PP + tid];
            float ax = ast_xy[2 * b], ay = ast_xy[2 * b + 1];
            float dx = pxy.x - ax;
            float dy = pxy.y - ay;
            float inv = rsqrtf(fmaf(dx, dx, fmaf(dy, dy, 1e-6f)));
            feats_s[tid] = make_float4(dx, dy, inv, mval);
        }
        __syncthreads();

        // per-batch partial sums (post-relu, accumulated over both halves)
        float s0[4], s1[4];
        #pragma unroll
        for (int n = 0; n < 4; ++n) { s0[n] = 0.f; s1[n] = 0.f; }

        #pragma unroll
        for (int half = 0; half < 2; ++half) {
            // ---- layer 1: 64 rows; thread does 16 rows of channel kk ----
            {
                const int rbase = rq * 16;
                #pragma unroll 16
                for (int i = 0; i < 16; ++i) {
                    int row = rbase + i;
                    float4 f = feats_s[half * 64 + row];   // warp-uniform broadcast
                    float hv = fmaf(f.x, w0, b1v);
                    hv = fmaf(f.y, w1, hv);
                    hv = fmaf(f.z, w2, hv);
                    hv = fmaf(f.w, w3, hv);
                    hv = fmaxf(hv, 0.0f);
                    h_s[row * HS_STRIDE + kk] = __uint_as_float(f2tf32(hv));
                }
            }
            __syncthreads();

            // ---- layer 2: warp: 16 rows x 32 cols, B from registers ----
            float c[4][4];
            #pragma unroll
            for (int n = 0; n < 4; ++n) {
                c[n][0] = 0.f; c[n][1] = 0.f; c[n][2] = 0.f; c[n][3] = 0.f;
            }
            const float* arow0 = &h_s[(mt * 16 + g)     * HS_STRIDE + tig];
            const float* arow1 = &h_s[(mt * 16 + g + 8) * HS_STRIDE + tig];
            #pragma unroll
            for (int kt = 0; kt < 8; ++kt) {
                uint32_t a0 = __float_as_uint(arow0[kt * 8]);
                uint32_t a1 = __float_as_uint(arow1[kt * 8]);
                uint32_t a2 = __float_as_uint(arow0[kt * 8 + 4]);
                uint32_t a3 = __float_as_uint(arow1[kt * 8 + 4]);
                #pragma unroll
                for (int n = 0; n < 4; ++n) {
                    asm volatile(
                        "mma.sync.aligned.m16n8k8.row.col.f32.tf32.tf32.f32 "
                        "{%0,%1,%2,%3}, {%4,%5,%6,%7}, {%8,%9}, {%0,%1,%2,%3};"
                        : "+f"(c[n][0]), "+f"(c[n][1]), "+f"(c[n][2]), "+f"(c[n][3])
                        : "r"(a0), "r"(a1), "r"(a2), "r"(a3),
                          "r"(brx[kt][n]), "r"(bry[kt][n]));
                }
            }

            // relu(+b2), fold this half's rows into register partials
            #pragma unroll
            for (int n = 0; n < 4; ++n) {
                int col0 = (nh * 4 + n) * 8 + 2 * tig;
                float bb0 = b2s[col0];
                float bb1 = b2s[col0 + 1];
                s0[n] += fmaxf(c[n][0] + bb0, 0.f) + fmaxf(c[n][2] + bb0, 0.f);
                s1[n] += fmaxf(c[n][1] + bb1, 0.f) + fmaxf(c[n][3] + bb1, 0.f);
            }
            __syncthreads();   // h_s consumed before next half rewrites
        }

        // ---- once per batch: reduce over g within warp, atomics across warps ----
        #pragma unroll
        for (int n = 0; n < 4; ++n) {
            float v0 = s0[n], v1 = s1[n];
            v0 += __shfl_xor_sync(0xffffffffu, v0, 4);
            v1 += __shfl_xor_sync(0xffffffffu, v1, 4);
            v0 += __shfl_xor_sync(0xffffffffu, v0, 8);
            v1 += __shfl_xor_sync(0xffffffffu, v1, 8);
            v0 += __shfl_xor_sync(0xffffffffu, v0, 16);
            v1 += __shfl_xor_sync(0xffffffffu, v1, 16);
            if (g == 0) {
                int col0 = (nh * 4 + n) * 8 + 2 * tig;
                atomicAdd(&sacc[col0],     v0);
                atomicAdd(&sacc[col0 + 1], v1);
            }
        }
        __syncthreads();

        if (tid < HH) out[b * HH + tid] = sacc[tid];
        __syncthreads();
    }
}

extern "C" void kernel_launch(void* const* d_in, const int* in_sizes, int n_in,
                              void* d_out, int out_size) {
    (void)in_sizes; (void)n_in; (void)out_size;
    const float* planet_xy = (const float*)d_in[0];
    const float* planet_m  = (const float*)d_in[1];
    const float* ast_xy    = (const float*)d_in[2];
    const float* W1        = (const float*)d_in[3];
    const float* b1        = (const float*)d_in[4];
    const float* W2        = (const float*)d_in[5];
    const float* b2        = (const float*)d_in[6];
    float* out             = (float*)d_out;

    gnn_kernel<<<GRID, 256>>>(planet_xy, planet_m, ast_xy, W1, b1, W2, b2, out);
}

// round 5
// speedup vs baseline: 3.2828x; 2.2968x over previous
#include <cuda_runtime.h>
#include <cuda_fp16.h>
#include <cstdint>

// SimpleGNNBlock: out[b,k] = sum_p relu( relu(feats[b,p,:] @ W1 + b1) @ W2 + b2 )
// feats = [dx, dy, 1/sqrt(dx^2+dy^2+1e-6), m_p],  B=32768, P=128, H=64.
//
// R5: both layers on tensor cores.
//  - Layer 1: m16n8k8 tf32, feats k-padded [dx,dy,inv,m,1,0,0,0] so b1 is
//    folded into the MMA. Output relu'd + packed to fp16x2 pairs in smem.
//  - Layer 2: m16n8k16 fp16 (same 10-bit mantissa as tf32), b2 folded via a
//    5th k-group bias MMA. Warp tile 64 rows x 16 cols -> B frags only 18 regs.
//  - 256 thr / 8 warps, __launch_bounds__(256,3): 3 CTAs/SM, 6 warps/SMSP.

#define BATCHES 32768
#define PP 128
#define HH 64
#define GRID 4096
#define BPC (BATCHES / GRID)    // 8
#define HW 36                   // h row stride in 32-bit words; 36%32==4 -> CF

__device__ __forceinline__ uint32_t f2tf32(float x) {
    uint32_t u;
    asm("cvt.rna.tf32.f32 %0, %1;" : "=r"(u) : "f"(x));
    return u;
}
// pack two fp32 -> f16x2 {lo, hi}
__device__ __forceinline__ uint32_t pack_f16(float lo, float hi) {
    uint32_t u;
    asm("cvt.rn.f16x2.f32 %0, %1, %2;" : "=r"(u) : "f"(hi), "f"(lo));
    return u;
}

__global__ __launch_bounds__(256, 3)
void gnn_kernel(const float* __restrict__ planet_xy,   // (B,P,2)
                const float* __restrict__ planet_m,    // (P)
                const float* __restrict__ ast_xy,      // (B,2)
                const float* __restrict__ W1,          // (4,H)
                const float* __restrict__ b1,          // (H)
                const float* __restrict__ W2,          // (H,H) [j][k]
                const float* __restrict__ b2,          // (H)
                float* __restrict__ out)               // (B,H)
{
    __shared__ uint32_t h2[128 * HW];   // h as fp16x2, row-major, stride HW words
    __shared__ uint4    feats_s[PP];    // tf32 bits {dx,dy,inv,m}
    __shared__ float    sacc[HH];

    const int tid  = threadIdx.x;
    const int lane = tid & 31;
    const int w    = tid >> 5;     // warp 0..7
    const int g    = lane >> 2;    // group 0..7
    const int t    = lane & 3;     // thread-in-group 0..3
    const int mg   = w >> 2;       // m-group 0..1 (rows mg*64 .. +63)
    const int ng   = w & 3;        // n-group 0..3 (cols ng*16 .. +15)

    // ---- W2 fp16 B-fragments (m16n8k16 row.col): b0={B[2t][g],B[2t+1][g]},
    //      b1={B[2t+8][g],B[2t+9][g]}, B[k][n]=W2[k][col], col=(ng*2+n2)*8+g.
    uint32_t b2f0[2][4], b2f1[2][4], bbias[2];
    #pragma unroll
    for (int n2 = 0; n2 < 2; ++n2) {
        int col = (ng * 2 + n2) * 8 + g;
        #pragma unroll
        for (int kt = 0; kt < 4; ++kt) {
            b2f0[n2][kt] = pack_f16(W2[(kt * 16 + 2 * t)     * HH + col],
                                    W2[(kt * 16 + 2 * t + 1) * HH + col]);
            b2f1[n2][kt] = pack_f16(W2[(kt * 16 + 2 * t + 8) * HH + col],
                                    W2[(kt * 16 + 2 * t + 9) * HH + col]);
        }
        bbias[n2] = (t == 0) ? pack_f16(b2[col], 0.0f) : 0u;
    }
    const uint32_t abias = (t == 0) ? 0x00003C00u : 0u;   // {lo=1.0h, hi=0}

    // ---- W1 tf32 B-fragments (m16n8k8): b0=B[t][col]=W1[t][col],
    //      b1=B[t+4][col] = b1[col] if t==0 (bias row), else 0.
    uint32_t w1x[8], w1y[8];
    #pragma unroll
    for (int n = 0; n < 8; ++n) {
        int col = n * 8 + g;
        w1x[n] = f2tf32(W1[t * HH + col]);
        w1y[n] = (t == 0) ? f2tf32(b1[col]) : 0u;
    }
    const uint32_t a1pad = (t == 0) ? 0x3f800000u : 0u;   // 1.0f (exact tf32)

    uint32_t m32 = 0;
    if (tid < PP) m32 = f2tf32(planet_m[tid]);

    if (tid < HH) sacc[tid] = 0.0f;

    for (int it = 0; it < BPC; ++it) {
        const int b = blockIdx.x + it * GRID;

        // ---- feats (tf32 bits) ----
        if (tid < PP) {
            float2 pxy = reinterpret_cast<const float2*>(planet_xy)[b * PP + tid];
            float ax = ast_xy[2 * b], ay = ast_xy[2 * b + 1];
            float dx = pxy.x - ax;
            float dy = pxy.y - ay;
            float inv = rsqrtf(fmaf(dx, dx, fmaf(dy, dy, 1e-6f)));
            feats_s[tid] = make_uint4(f2tf32(dx), f2tf32(dy), f2tf32(inv), m32);
        }
        __syncthreads();

        // ---- layer 1: warp w owns m-tile w (16 rows), all 8 col-tiles ----
        {
            const uint32_t* fu = reinterpret_cast<const uint32_t*>(feats_s);
            uint32_t a0 = fu[(w * 16 + g)     * 4 + t];
            uint32_t a1 = fu[(w * 16 + g + 8) * 4 + t];
            #pragma unroll
            for (int n = 0; n < 8; ++n) {
                float c0 = 0.f, c1 = 0.f, c2 = 0.f, c3 = 0.f;
                asm volatile(
                    "mma.sync.aligned.m16n8k8.row.col.f32.tf32.tf32.f32 "
                    "{%0,%1,%2,%3}, {%4,%5,%6,%7}, {%8,%9}, {%0,%1,%2,%3};"
                    : "+f"(c0), "+f"(c1), "+f"(c2), "+f"(c3)
                    : "r"(a0), "r"(a1), "r"(a1pad), "r"(a1pad),
                      "r"(w1x[n]), "r"(w1y[n]));
                uint32_t p0 = pack_f16(fmaxf(c0, 0.f), fmaxf(c1, 0.f));
                uint32_t p1 = pack_f16(fmaxf(c2, 0.f), fmaxf(c3, 0.f));
                h2[(w * 16 + g)     * HW + n * 4 + t] = p0;
                h2[(w * 16 + g + 8) * HW + n * 4 + t] = p1;
            }
        }
        __syncthreads();

        // ---- layer 2: warp covers rows mg*64..+63 (4 m-tiles), 2 n-tiles ----
        float s0[2] = {0.f, 0.f}, s1[2] = {0.f, 0.f};
        #pragma unroll
        for (int mt = 0; mt < 4; ++mt) {
            const int r0 = mg * 64 + mt * 16 + g;
            float c[2][4];
            #pragma unroll
            for (int n2 = 0; n2 < 2; ++n2) {
                c[n2][0] = 0.f; c[n2][1] = 0.f; c[n2][2] = 0.f; c[n2][3] = 0.f;
            }
            #pragma unroll
            for (int kt = 0; kt < 4; ++kt) {
                uint32_t a0 = h2[r0       * HW + kt * 8 + t];
                uint32_t a1 = h2[(r0 + 8) * HW + kt * 8 + t];
                uint32_t a2 = h2[r0       * HW + kt * 8 + t + 4];
                uint32_t a3 = h2[(r0 + 8) * HW + kt * 8 + t + 4];
                #pragma unroll
                for (int n2 = 0; n2 < 2; ++n2) {
                    asm volatile(
                        "mma.sync.aligned.m16n8k16.row.col.f32.f16.f16.f32 "
                        "{%0,%1,%2,%3}, {%4,%5,%6,%7}, {%8,%9}, {%0,%1,%2,%3};"
                        : "+f"(c[n2][0]), "+f"(c[n2][1]), "+f"(c[n2][2]), "+f"(c[n2][3])
                        : "r"(a0), "r"(a1), "r"(a2), "r"(a3),
                          "r"(b2f0[n2][kt]), "r"(b2f1[n2][kt]));
                }
            }
            // bias k-group: A cols 64..79 = [1,0,...], B rows 64..79 = [b2;0..]
            #pragma unroll
            for (int n2 = 0; n2 < 2; ++n2) {
                asm volatile(
                    "mma.sync.aligned.m16n8k16.row.col.f32.f16.f16.f32 "
                    "{%0,%1,%2,%3}, {%4,%5,%6,%7}, {%8,%9}, {%0,%1,%2,%3};"
                    : "+f"(c[n2][0]), "+f"(c[n2][1]), "+f"(c[n2][2]), "+f"(c[n2][3])
                    : "r"(abias), "r"(abias), "r"(0u), "r"(0u),
                      "r"(bbias[n2]), "r"(0u));
                s0[n2] += fmaxf(c[n2][0], 0.f) + fmaxf(c[n2][2], 0.f);
                s1[n2] += fmaxf(c[n2][1], 0.f) + fmaxf(c[n2][3], 0.f);
            }
        }

        // ---- reduce: over g via shuffles, across warps via smem atomics ----
        #pragma unroll
        for (int n2 = 0; n2 < 2; ++n2) {
            float v0 = s0[n2], v1 = s1[n2];
            v0 += __shfl_xor_sync(0xffffffffu, v0, 4);
            v1 += __shfl_xor_sync(0xffffffffu, v1, 4);
            v0 += __shfl_xor_sync(0xffffffffu, v0, 8);
            v1 += __shfl_xor_sync(0xffffffffu, v1, 8);
            v0 += __shfl_xor_sync(0xffffffffu, v0, 16);
            v1 += __shfl_xor_sync(0xffffffffu, v1, 16);
            if (g == 0) {
                int col0 = (ng * 2 + n2) * 8 + 2 * t;
                atomicAdd(&sacc[col0],     v0);
                atomicAdd(&sacc[col0 + 1], v1);
            }
        }
        __syncthreads();

        if (tid < HH) {
            out[b * HH + tid] = sacc[tid];
            sacc[tid] = 0.0f;          // re-zero for next batch
        }
        // no tail sync needed: sacc next touched (atomics) only after two
        // more __syncthreads(); feats_s/h2 rewrites likewise fenced.
    }
}

extern "C" void kernel_launch(void* const* d_in, const int* in_sizes, int n_in,
                              void* d_out, int out_size) {
    (void)in_sizes; (void)n_in; (void)out_size;
    const float* planet_xy = (const float*)d_in[0];
    const float* planet_m  = (const float*)d_in[1];
    const float* ast_xy    = (const float*)d_in[2];
    const float* W1        = (const float*)d_in[3];
    const float* b1        = (const float*)d_in[4];
    const float* W2        = (const float*)d_in[5];
    const float* b2        = (const float*)d_in[6];
    float* out             = (float*)d_out;

    gnn_kernel<<<GRID, 256>>>(planet_xy, planet_m, ast_xy, W1, b1, W2, b2, out);
}